// round 11
// baseline (speedup 1.0000x reference)
#include <cuda_runtime.h>
#include <cstdint>

// Problem: inputs [8,128,128,64] f32, beta [64,16] f32
// out[e, c] = inputs[e] * u[e%64, c],  u = beta^2 / rowsum(beta^2)
// out flat: 2^29 floats = 2^24 32-byte granules (8 floats each).
//
// R11: R3's winning shape (1024 blocks x 256 thr, batch-8 loads, dense
// strided sweep) but with 256-bit stores (st.global.cs.v8.f32, sm_100+).
// Thread handles granule g: input element e = g>>1, half h = g&1; its
// 8-element u half-row is loop-invariant (stride is a multiple of 128).

#define D_DIM 64
#define BLOCKS 1024
#define THREADS 256
#define NTHREADS (BLOCKS * THREADS)        // 2^18 granule-stride
#define N_GRAN (1u << 24)                  // total 8-float granules
#define ITERS 64                           // N_GRAN / NTHREADS
#define BATCH 8
#define PASSES (ITERS / BATCH)             // 8

__device__ __forceinline__ void stg_cs_v8(float* p, const float* v) {
    asm volatile(
        "st.global.cs.v8.f32 [%0], {%1,%2,%3,%4,%5,%6,%7,%8};"
        :: "l"(p), "f"(v[0]), "f"(v[1]), "f"(v[2]), "f"(v[3]),
           "f"(v[4]), "f"(v[5]), "f"(v[6]), "f"(v[7])
        : "memory");
}

__global__ void __launch_bounds__(THREADS) fused_broadcast_mul_v8(
    const float* __restrict__ in, const float* __restrict__ beta,
    float* __restrict__ out) {
    const unsigned int g = blockIdx.x * THREADS + threadIdx.x;  // granule idx
    const unsigned int e0 = g >> 1;                 // first input element
    const unsigned int i = e0 & (D_DIM - 1);        // beta row
    const unsigned int h = g & 1u;                  // which 8-float half of row

    // ---- prologue: this thread's 8-element u half-row, in registers ----
    const float4* br = reinterpret_cast<const float4*>(beta) + i * 4;
    float4 q0 = __ldg(br + 0);
    float4 q1 = __ldg(br + 1);
    float4 q2 = __ldg(br + 2);
    float4 q3 = __ldg(br + 3);
    float s = q0.x * q0.x + q0.y * q0.y + q0.z * q0.z + q0.w * q0.w
            + q1.x * q1.x + q1.y * q1.y + q1.z * q1.z + q1.w * q1.w
            + q2.x * q2.x + q2.y * q2.y + q2.z * q2.z + q2.w * q2.w
            + q3.x * q3.x + q3.y * q3.y + q3.z * q3.z + q3.w * q3.w;
    float inv = 1.0f / s;
    float4 a = h ? q2 : q0;
    float4 b = h ? q3 : q1;
    float u[8];
    u[0] = a.x * a.x * inv; u[1] = a.y * a.y * inv;
    u[2] = a.z * a.z * inv; u[3] = a.w * a.w * inv;
    u[4] = b.x * b.x * inv; u[5] = b.y * b.y * inv;
    u[6] = b.z * b.z * inv; u[7] = b.w * b.w * inv;

    // ---- 8 passes: 8 independent loads, then 8 v8 (32B) stores ----
    const float* ip = in + e0;            // advances NTHREADS/2 elems per k
    float* op = out + (size_t)g * 8;      // advances NTHREADS granules per k

    for (int p = 0; p < PASSES; ++p) {
        float x[BATCH];
#pragma unroll
        for (int k = 0; k < BATCH; ++k)
            x[k] = __ldg(ip + k * (NTHREADS / 2));   // input fits L2
#pragma unroll
        for (int k = 0; k < BATCH; ++k) {
            float r[8];
#pragma unroll
            for (int c = 0; c < 8; ++c) r[c] = x[k] * u[c];
            stg_cs_v8(op + (size_t)k * NTHREADS * 8, r);
        }
        ip += (NTHREADS / 2) * BATCH;
        op += (size_t)NTHREADS * 8 * BATCH;
    }
}

extern "C" void kernel_launch(void* const* d_in, const int* in_sizes, int n_in,
                              void* d_out, int out_size) {
    const float* inputs = (const float*)d_in[0];  // 8*128*128*64 = 8388608
    const float* beta   = (const float*)d_in[1];  // 64*16 = 1024
    float* out = (float*)d_out;

    fused_broadcast_mul_v8<<<BLOCKS, THREADS>>>(inputs, beta, out);
}

// round 12
// speedup vs baseline: 1.0207x; 1.0207x over previous
#include <cuda_runtime.h>

// Problem: inputs [8,128,128,64] f32, beta [64,16] f32
// out[e, c] = inputs[e] * u[e%64, c],  u = beta^2 / rowsum(beta^2)
// out flat: n4 = 2^25 float4s. (i = (g>>2)&63, j = g&3) has period 256 in g;
// grid stride is a multiple of 256 -> per-thread u is loop-invariant.
//
// R12 = R3 verbatim (best: 92.3us) with ONE change: default .wb stores
// instead of .cs. Hypothesis: evict-first caused eager partial-line (32B
// sector) writebacks to DRAM; .wb lets L2 evict full 128B lines.

#define D_DIM 64
#define BLOCKS 1024
#define THREADS 256
#define STRIDE (BLOCKS * THREADS)      // 2^18 float4s per grid step
#define ITERS 128                      // 2^25 / STRIDE
#define BATCH 8
#define PASSES (ITERS / BATCH)         // 16

__global__ void __launch_bounds__(THREADS) fused_broadcast_mul(
    const float* __restrict__ in, const float* __restrict__ beta,
    float4* __restrict__ out) {
    unsigned int g = blockIdx.x * THREADS + threadIdx.x;
    const unsigned int i = (g >> 2) & (D_DIM - 1);  // beta row
    const unsigned int j = g & 3u;                  // float4 quarter of the row

    // ---- one-time prologue: this thread's u quarter, in registers ----
    const float4* br = reinterpret_cast<const float4*>(beta) + i * 4;
    float4 q0 = __ldg(br + 0);
    float4 q1 = __ldg(br + 1);
    float4 q2 = __ldg(br + 2);
    float4 q3 = __ldg(br + 3);
    float s = q0.x * q0.x + q0.y * q0.y + q0.z * q0.z + q0.w * q0.w
            + q1.x * q1.x + q1.y * q1.y + q1.z * q1.z + q1.w * q1.w
            + q2.x * q2.x + q2.y * q2.y + q2.z * q2.z + q2.w * q2.w
            + q3.x * q3.x + q3.y * q3.y + q3.z * q3.z + q3.w * q3.w;
    float inv = 1.0f / s;
    float4 bq = (j == 0) ? q0 : (j == 1) ? q1 : (j == 2) ? q2 : q3;
    const float4 u = make_float4(bq.x * bq.x * inv, bq.y * bq.y * inv,
                                 bq.z * bq.z * inv, bq.w * bq.w * inv);

    // ---- 16 passes: 8 independent loads, then 8 FMUL+STG.128 (.wb) ----
    const float* ip = in + (g >> 2);
    float4* op = out + g;

    for (int p = 0; p < PASSES; ++p) {
        float x[BATCH];
#pragma unroll
        for (int k = 0; k < BATCH; ++k)
            x[k] = __ldg(ip + k * (STRIDE / 4));
#pragma unroll
        for (int k = 0; k < BATCH; ++k) {
            float4 r = make_float4(x[k] * u.x, x[k] * u.y,
                                   x[k] * u.z, x[k] * u.w);
            op[k * STRIDE] = r;                    // default .wb store
        }
        ip += (STRIDE / 4) * BATCH;
        op += STRIDE * BATCH;
    }
}

extern "C" void kernel_launch(void* const* d_in, const int* in_sizes, int n_in,
                              void* d_out, int out_size) {
    const float* inputs = (const float*)d_in[0];  // 8*128*128*64 = 8388608
    const float* beta   = (const float*)d_in[1];  // 64*16 = 1024
    float4* out = (float4*)d_out;

    fused_broadcast_mul<<<BLOCKS, THREADS>>>(inputs, beta, out);
}